// round 1
// baseline (speedup 1.0000x reference)
#include <cuda_runtime.h>
#include <math.h>

// NT-Xent loss: feat1 [4096,128] fp32, feat2 [4096,128] fp32 -> scalar loss.
// features = normalize(concat(feat1,feat2))  [8192,128]
// logits = F F^T / T ; per row i: sum_{j!=i} exp(l_ij - l_ii) ; pos = l_{i,(i+N)%2N} - l_ii
// log_prob = pos - log(sum) ; loss = -mean(log_prob)   (T/BASE_T == 1)
// Shift by constant 1/T (== row max up to float dust; shift cancels exactly in pos - log(sum)).

#define TWO_N   8192
#define N_HALF  4096
#define CDIM    128
#define INV_T   14.285714285714286f   // 1/0.07

#define TM      64     // rows per block
#define TC      128    // cols per chunk
#define PAD_A   65     // sA stride (k-major), conflict-free
#define PAD_B   129    // sB stride (k-major), conflict-free
#define SMEM_FLOATS (CDIM*PAD_A + CDIM*PAD_B)
#define SMEM_BYTES  (SMEM_FLOATS * 4)

__device__ float g_Fn[TWO_N * CDIM];   // normalized features
__device__ float g_rowlog[TWO_N];      // per-row log_prob

// ---------------------------------------------------------------------------
// Kernel 1: concat + L2-normalize rows. One block (128 threads) per row.
// ---------------------------------------------------------------------------
__global__ void normalize_kernel(const float* __restrict__ f1,
                                 const float* __restrict__ f2) {
    int row = blockIdx.x;
    int t   = threadIdx.x;
    const float* src = (row < N_HALF) ? (f1 + (size_t)row * CDIM)
                                      : (f2 + (size_t)(row - N_HALF) * CDIM);
    float v = src[t];
    float s = v * v;
    #pragma unroll
    for (int o = 16; o; o >>= 1) s += __shfl_xor_sync(0xffffffffu, s, o);
    __shared__ float ws[4];
    if ((t & 31) == 0) ws[t >> 5] = s;
    __syncthreads();
    float tot  = ws[0] + ws[1] + ws[2] + ws[3];
    float norm = fmaxf(sqrtf(tot), 1e-12f);
    g_Fn[(size_t)row * CDIM + t] = v / norm;
}

// ---------------------------------------------------------------------------
// Kernel 2: tiled F F^T with fused exp-sum + positive-pair capture.
// Block: 64 rows, loops over 64 chunks of 128 cols. 256 threads = 16x16.
// Thread (tx,ty): rows r = ty + 16*rr (rr<4), cols c = tx + 16*cc (cc<8).
// ---------------------------------------------------------------------------
extern __shared__ float smem[];

__global__ void __launch_bounds__(256, 1) ntxent_main_kernel() {
    float* sA = smem;                    // [CDIM][PAD_A] k-major, rows tile
    float* sB = smem + CDIM * PAD_A;     // [CDIM][PAD_B] k-major, cols tile

    int tid = threadIdx.x;
    int tx  = tid & 15;
    int ty  = tid >> 4;
    int rowBase = blockIdx.x * TM;

    // Load A tile (64 rows x 128), transposed to k-major. float4 gmem reads.
    for (int idx = tid; idx < TM * (CDIM / 4); idx += 256) {
        int r  = idx >> 5;          // 32 float4 per row
        int f4 = idx & 31;
        float4 v = *(const float4*)(g_Fn + (size_t)(rowBase + r) * CDIM + f4 * 4);
        sA[(f4 * 4 + 0) * PAD_A + r] = v.x;
        sA[(f4 * 4 + 1) * PAD_A + r] = v.y;
        sA[(f4 * 4 + 2) * PAD_A + r] = v.z;
        sA[(f4 * 4 + 3) * PAD_A + r] = v.w;
    }

    int gr[4], tcol[4];
    float rowAcc[4] = {0.f, 0.f, 0.f, 0.f};
    float posAcc[4] = {0.f, 0.f, 0.f, 0.f};
    #pragma unroll
    for (int rr = 0; rr < 4; rr++) {
        gr[rr]   = rowBase + ty + 16 * rr;
        tcol[rr] = (gr[rr] + N_HALF) & (TWO_N - 1);
    }

    for (int cb = 0; cb < TWO_N / TC; cb++) {
        int colBase = cb * TC;
        __syncthreads();   // previous chunk's sB reads done (also covers sA stores, iter 0)
        for (int idx = tid; idx < TC * (CDIM / 4); idx += 256) {
            int c  = idx >> 5;
            int f4 = idx & 31;
            float4 v = *(const float4*)(g_Fn + (size_t)(colBase + c) * CDIM + f4 * 4);
            sB[(f4 * 4 + 0) * PAD_B + c] = v.x;
            sB[(f4 * 4 + 1) * PAD_B + c] = v.y;
            sB[(f4 * 4 + 2) * PAD_B + c] = v.z;
            sB[(f4 * 4 + 3) * PAD_B + c] = v.w;
        }
        __syncthreads();

        float acc[4][8];
        #pragma unroll
        for (int rr = 0; rr < 4; rr++)
            #pragma unroll
            for (int cc = 0; cc < 8; cc++) acc[rr][cc] = 0.f;

        #pragma unroll 8
        for (int k = 0; k < CDIM; k++) {
            float a[4], b[8];
            #pragma unroll
            for (int rr = 0; rr < 4; rr++) a[rr] = sA[k * PAD_A + ty + 16 * rr];
            #pragma unroll
            for (int cc = 0; cc < 8; cc++) b[cc] = sB[k * PAD_B + tx + 16 * cc];
            #pragma unroll
            for (int rr = 0; rr < 4; rr++)
                #pragma unroll
                for (int cc = 0; cc < 8; cc++)
                    acc[rr][cc] = fmaf(a[rr], b[cc], acc[rr][cc]);
        }

        // Fused epilogue: shifted logits, exp-sum (excl. diagonal), pos capture.
        #pragma unroll
        for (int rr = 0; rr < 4; rr++) {
            #pragma unroll
            for (int cc = 0; cc < 8; cc++) {
                int   gc = colBase + tx + 16 * cc;
                float l  = (acc[rr][cc] - 1.0f) * INV_T;   // l_ij - 1/T (row-max shift)
                float e  = __expf(l);
                if (gc != gr[rr])   rowAcc[rr] += e;
                if (gc == tcol[rr]) posAcc[rr] += l;       // exactly one hit per row
            }
        }
    }

    // Block reduction across the 16 col-groups sharing each row. Deterministic.
    __syncthreads();
    float* redS = smem;              // [64][17]
    float* redP = smem + 64 * 17;    // [64][17]
    #pragma unroll
    for (int rr = 0; rr < 4; rr++) {
        int r = ty + 16 * rr;
        redS[r * 17 + tx] = rowAcc[rr];
        redP[r * 17 + tx] = posAcc[rr];
    }
    __syncthreads();
    if (tid < TM) {
        float s = 0.f, p = 0.f;
        #pragma unroll
        for (int x = 0; x < 16; x++) {
            s += redS[tid * 17 + x];
            p += redP[tid * 17 + x];
        }
        g_rowlog[rowBase + tid] = p - logf(s);
    }
}

// ---------------------------------------------------------------------------
// Kernel 3: deterministic final reduction -> -mean(log_prob)
// ---------------------------------------------------------------------------
__global__ void reduce_kernel(float* __restrict__ out) {
    __shared__ double sm[256];
    int t = threadIdx.x;
    double s = 0.0;
    for (int i = t; i < TWO_N; i += 256) s += (double)g_rowlog[i];
    sm[t] = s;
    __syncthreads();
    #pragma unroll
    for (int o = 128; o; o >>= 1) {
        if (t < o) sm[t] += sm[t + o];
        __syncthreads();
    }
    if (t == 0) out[0] = (float)(-sm[0] / (double)TWO_N);
}

// ---------------------------------------------------------------------------
extern "C" void kernel_launch(void* const* d_in, const int* in_sizes, int n_in,
                              void* d_out, int out_size) {
    const float* f1 = (const float*)d_in[0];
    const float* f2 = (const float*)d_in[1];
    float* out = (float*)d_out;

    cudaFuncSetAttribute(ntxent_main_kernel,
                         cudaFuncAttributeMaxDynamicSharedMemorySize, SMEM_BYTES);

    normalize_kernel<<<TWO_N, CDIM>>>(f1, f2);
    ntxent_main_kernel<<<TWO_N / TM, 256, SMEM_BYTES>>>();
    reduce_kernel<<<1, 256>>>(out);
}

// round 3
// speedup vs baseline: 7.7480x; 7.7480x over previous
#include <cuda_runtime.h>
#include <cuda_bf16.h>
#include <math.h>
#include <stdint.h>

// NT-Xent via mma.sync (HMMA bf16) — tcgen05 not assemblable in this harness
// (ptxas target sm_103 plain). S = F F^T, K=128, fused exp epilogue in registers.
//
// Grid: 64 row-blocks x 2 column halves = 128 CTAs. CTA: 256 thr = 8 warps,
// warp grid 2(m) x 4(n), warp tile 64x32, mma m16n8k16, K unrolled 8 steps.
// Smem: A tile (128x128 bf16) resident; B tiles double-buffered via cp.async.
// Tile rows padded to 272B so ldmatrix 8-row reads are bank-conflict-free.

#define TWO_N   8192
#define N_HALF  4096
#define CDIM    128
#define INV_T   14.285714285714286f          // 1/0.07
#define K1      20.60984248218323f           // INV_T * log2(e)

#define TSTRIDE 272
#define TILEB   (128 * TSTRIDE)
#define SMEM_DYN (3 * TILEB)

__device__ __align__(16) __nv_bfloat16 g_Fbf[TWO_N * CDIM];
__device__ float g_sumpart[2 * TWO_N];
__device__ float g_pospart[2 * TWO_N];

__device__ __forceinline__ uint32_t smem_u32(const void* p) {
    uint32_t a;
    asm("{ .reg .u64 t; cvta.to.shared.u64 t, %1; cvt.u32.u64 %0, t; }"
        : "=r"(a) : "l"(p));
    return a;
}
__device__ __forceinline__ float ex2f(float x) {
    float r;
    asm("ex2.approx.ftz.f32 %0, %1;" : "=f"(r) : "f"(x));
    return r;
}
__device__ __forceinline__ void cp16(uint32_t s, const void* g) {
    asm volatile("cp.async.cg.shared.global [%0], [%1], 16;" :: "r"(s), "l"(g));
}
#define CP_COMMIT() asm volatile("cp.async.commit_group;" ::: "memory")
#define CP_WAIT1()  asm volatile("cp.async.wait_group 1;" ::: "memory")
#define CP_WAIT0()  asm volatile("cp.async.wait_group 0;" ::: "memory")

#define LDSM_X4(r0, r1, r2, r3, addr)                                          \
    asm volatile("ldmatrix.sync.aligned.m8n8.x4.shared.b16 {%0,%1,%2,%3},[%4];"\
        : "=r"(r0), "=r"(r1), "=r"(r2), "=r"(r3) : "r"(addr))

#define MMA16816(c, a, b0, b1)                                                 \
    asm volatile("mma.sync.aligned.m16n8k16.row.col.f32.bf16.bf16.f32 "        \
        "{%0,%1,%2,%3},{%4,%5,%6,%7},{%8,%9},{%0,%1,%2,%3};"                   \
        : "+f"((c)[0]), "+f"((c)[1]), "+f"((c)[2]), "+f"((c)[3])               \
        : "r"((a)[0]), "r"((a)[1]), "r"((a)[2]), "r"((a)[3]),                  \
          "r"(b0), "r"(b1))

// ---------------------------------------------------------------------------
// Kernel 1: L2-normalize + bf16 convert. 1 warp per row.
// ---------------------------------------------------------------------------
__global__ void normalize_kernel(const float* __restrict__ f1,
                                 const float* __restrict__ f2) {
    int wid  = threadIdx.x >> 5;
    int lane = threadIdx.x & 31;
    int row  = blockIdx.x * 8 + wid;
    const float* src = (row < N_HALF) ? (f1 + (size_t)row * CDIM)
                                      : (f2 + (size_t)(row - N_HALF) * CDIM);
    float4 v = *(const float4*)(src + lane * 4);
    float s = v.x * v.x + v.y * v.y + v.z * v.z + v.w * v.w;
    #pragma unroll
    for (int o = 16; o; o >>= 1) s += __shfl_xor_sync(0xffffffffu, s, o);
    float inv = 1.0f / fmaxf(sqrtf(s), 1e-12f);
    __nv_bfloat162 p0 = __floats2bfloat162_rn(v.x * inv, v.y * inv);
    __nv_bfloat162 p1 = __floats2bfloat162_rn(v.z * inv, v.w * inv);
    uint2 u;
    u.x = *(uint32_t*)&p0;
    u.y = *(uint32_t*)&p1;
    *(uint2*)(g_Fbf + (size_t)row * CDIM + lane * 4) = u;
}

// ---------------------------------------------------------------------------
// Kernel 2: HMMA main.
// ---------------------------------------------------------------------------
extern __shared__ char dynsmem[];

__global__ void __launch_bounds__(256, 1) ntxent_mma_kernel() {
    const int tid  = threadIdx.x;
    const int lane = tid & 31;
    const int wid  = tid >> 5;
    const int wm   = wid & 1;        // warp row 0..1 (64 rows each)
    const int wn   = wid >> 1;       // warp col 0..3 (32 cols each)

    const int bx       = blockIdx.x;
    const int rowBase  = (bx >> 1) << 7;
    const int half     = bx & 1;
    const int colStart = half << 12;

    char* sA = dynsmem;
    uint32_t sAu = smem_u32(sA);
    uint32_t sBu[2] = { sAu + TILEB, sAu + 2 * TILEB };

    // Prologue: async-load A tile, B0, B1.
    {
        const char* gA  = (const char*)(g_Fbf + (size_t)rowBase * CDIM);
        const char* gB0 = (const char*)(g_Fbf + (size_t)colStart * CDIM);
        const char* gB1 = (const char*)(g_Fbf + (size_t)(colStart + 128) * CDIM);
        #pragma unroll
        for (int i = 0; i < 8; i++) {
            int idx = tid + i * 256, r = idx >> 4, c = idx & 15;
            cp16(sAu + r * TSTRIDE + c * 16, gA + r * 256 + c * 16);
            cp16(sBu[0] + r * TSTRIDE + c * 16, gB0 + r * 256 + c * 16);
        }
        CP_COMMIT();
        #pragma unroll
        for (int i = 0; i < 8; i++) {
            int idx = tid + i * 256, r = idx >> 4, c = idx & 15;
            cp16(sBu[1] + r * TSTRIDE + c * 16, gB1 + r * 256 + c * 16);
        }
        CP_COMMIT();
    }
    CP_WAIT1();
    __syncthreads();

    // ldmatrix per-thread base addresses.
    // A (x4): lanes 0-15 -> rows (lane&15) @+0B, lanes 16-31 -> same rows @+16B.
    uint32_t aBase = sAu + (uint32_t)((wm * 64 + (lane & 15)) * TSTRIDE)
                         + (uint32_t)((lane >> 4) * 16);
    // B (x4, two n-tiles): row = wn*32 + np*16 + (lane&7) + ((lane>>4)&1)*8,
    // byte offset ((lane>>3)&1)*16.
    uint32_t bRowOff = (uint32_t)((wn * 32 + (lane & 7) + ((lane >> 4) & 1) * 8) * TSTRIDE)
                     + (uint32_t)(((lane >> 3) & 1) * 16);

    float rowAcc[8], posAcc[8];
    #pragma unroll
    for (int i = 0; i < 8; i++) { rowAcc[i] = 0.f; posAcc[i] = 0.f; }

    const int diagCb = ((rowBase >> 12) == half) ? ((rowBase - colStart) >> 7) : -1;
    const int pcBase = (rowBase + N_HALF) & (TWO_N - 1);
    const int posCb  = ((pcBase >> 12) == half) ? ((pcBase - colStart) >> 7) : -1;

    for (int cb = 0; cb < 32; cb++) {
        const int cur = cb & 1;
        const uint32_t sBc = sBu[cur];

        float acc[4][4][4];
        #pragma unroll
        for (int mi = 0; mi < 4; mi++)
            #pragma unroll
            for (int ni = 0; ni < 4; ni++)
                #pragma unroll
                for (int rg = 0; rg < 4; rg++) acc[mi][ni][rg] = 0.f;

        #pragma unroll
        for (int ks = 0; ks < 8; ks++) {
            uint32_t afr[4][4], bfr[2][4];
            #pragma unroll
            for (int mi = 0; mi < 4; mi++) {
                uint32_t ad = aBase + (uint32_t)(mi * 16 * TSTRIDE + ks * 32);
                LDSM_X4(afr[mi][0], afr[mi][1], afr[mi][2], afr[mi][3], ad);
            }
            #pragma unroll
            for (int np = 0; np < 2; np++) {
                uint32_t bd = sBc + bRowOff + (uint32_t)(np * 16 * TSTRIDE + ks * 32);
                LDSM_X4(bfr[np][0], bfr[np][1], bfr[np][2], bfr[np][3], bd);
            }
            #pragma unroll
            for (int mi = 0; mi < 4; mi++)
                #pragma unroll
                for (int ni = 0; ni < 4; ni++)
                    MMA16816(acc[mi][ni], afr[mi],
                             bfr[ni >> 1][(ni & 1) * 2],
                             bfr[ni >> 1][(ni & 1) * 2 + 1]);
        }

        // Fused epilogue: exp((s-1)/T) row sums (branch-free).
        #pragma unroll
        for (int mi = 0; mi < 4; mi++)
            #pragma unroll
            for (int ni = 0; ni < 4; ni++)
                #pragma unroll
                for (int rg = 0; rg < 4; rg++)
                    rowAcc[mi * 2 + (rg >> 1)] +=
                        ex2f(fmaf(acc[mi][ni][rg], K1, -K1));

        // Rare chunks: diagonal exclusion / positive-pair capture.
        // Target element in both cases satisfies col_in_chunk == row_in_block.
        if (cb == diagCb || cb == posCb) {
            const bool isDiag = (cb == diagCb);
            #pragma unroll
            for (int mi = 0; mi < 4; mi++)
                #pragma unroll
                for (int ni = 0; ni < 4; ni++)
                    #pragma unroll
                    for (int rg = 0; rg < 4; rg++) {
                        int rl = wm * 64 + mi * 16 + (lane >> 2) + 8 * (rg >> 1);
                        int cl = wn * 32 + ni * 8 + (lane & 3) * 2 + (rg & 1);
                        if (cl == rl) {
                            float f = acc[mi][ni][rg];
                            if (isDiag)
                                rowAcc[mi * 2 + (rg >> 1)] -= ex2f(fmaf(f, K1, -K1));
                            else
                                posAcc[mi * 2 + (rg >> 1)] += (f - 1.0f) * INV_T;
                        }
                    }
        }

        __syncthreads();                     // all warps done reading buf cur
        if (cb + 2 < 32) {
            const char* gB = (const char*)(g_Fbf + (size_t)(colStart + (cb + 2) * 128) * CDIM);
            #pragma unroll
            for (int i = 0; i < 8; i++) {
                int idx = tid + i * 256, r = idx >> 4, c = idx & 15;
                cp16(sBu[cur] + r * TSTRIDE + c * 16, gB + r * 256 + c * 16);
            }
            CP_COMMIT();
        }
        if (cb + 1 < 32) {
            if (cb + 2 < 32) CP_WAIT1(); else CP_WAIT0();
            __syncthreads();
        }
    }

    // Intra-warp: combine 4 lanes sharing each row (lanes differ in t%4 = cols).
    #pragma unroll
    for (int h = 0; h < 8; h++) {
        rowAcc[h] += __shfl_xor_sync(0xffffffffu, rowAcc[h], 1);
        rowAcc[h] += __shfl_xor_sync(0xffffffffu, rowAcc[h], 2);
        posAcc[h] += __shfl_xor_sync(0xffffffffu, posAcc[h], 1);
        posAcc[h] += __shfl_xor_sync(0xffffffffu, posAcc[h], 2);
    }
    __syncthreads();                         // compute smem no longer needed
    float* sRed = (float*)dynsmem;           // [128][4]
    float* sPos = (float*)dynsmem + 512;     // [128][4]
    if ((lane & 3) == 0) {
        #pragma unroll
        for (int h = 0; h < 8; h++) {
            int r = wm * 64 + (h >> 1) * 16 + (lane >> 2) + 8 * (h & 1);
            sRed[r * 4 + wn] = rowAcc[h];
            sPos[r * 4 + wn] = posAcc[h];
        }
    }
    __syncthreads();
    if (tid < 128) {
        float s = sRed[tid * 4] + sRed[tid * 4 + 1] + sRed[tid * 4 + 2] + sRed[tid * 4 + 3];
        float p = sPos[tid * 4] + sPos[tid * 4 + 1] + sPos[tid * 4 + 2] + sPos[tid * 4 + 3];
        g_sumpart[half * TWO_N + rowBase + tid] = s;
        g_pospart[half * TWO_N + rowBase + tid] = p;
    }
}

// ---------------------------------------------------------------------------
// Kernel 3: deterministic final reduction.
// ---------------------------------------------------------------------------
__global__ void reduce_kernel(float* __restrict__ out) {
    __shared__ double sm[256];
    int t = threadIdx.x;
    double s = 0.0;
    for (int i = t; i < TWO_N; i += 256) {
        float sum = g_sumpart[i] + g_sumpart[TWO_N + i];
        float pos = g_pospart[i] + g_pospart[TWO_N + i];
        s += (double)(pos - logf(sum));
    }
    sm[t] = s;
    __syncthreads();
    #pragma unroll
    for (int o = 128; o; o >>= 1) {
        if (t < o) sm[t] += sm[t + o];
        __syncthreads();
    }
    if (t == 0) out[0] = (float)(-sm[0] / (double)TWO_N);
}

// ---------------------------------------------------------------------------
extern "C" void kernel_launch(void* const* d_in, const int* in_sizes, int n_in,
                              void* d_out, int out_size) {
    const float* f1 = (const float*)d_in[0];
    const float* f2 = (const float*)d_in[1];
    float* out = (float*)d_out;

    cudaFuncSetAttribute(ntxent_mma_kernel,
                         cudaFuncAttributeMaxDynamicSharedMemorySize, SMEM_DYN);

    normalize_kernel<<<TWO_N / 8, 256>>>(f1, f2);
    ntxent_mma_kernel<<<128, 256, SMEM_DYN>>>();
    reduce_kernel<<<1, 256>>>(out);
}

// round 4
// speedup vs baseline: 8.3814x; 1.0817x over previous
#include <cuda_runtime.h>
#include <cuda_bf16.h>
#include <math.h>
#include <stdint.h>

// NT-Xent via mma.sync (HMMA bf16). S = F F^T, K=128.
// R4: epilogue of chunk cb-1 interleaved into K-loop of chunk cb
// (double-buffered register accumulators) so MUFU/FADD hide under tensor pipe.

#define TWO_N   8192
#define N_HALF  4096
#define CDIM    128
#define INV_T   14.285714285714286f          // 1/0.07
#define K1      20.60984248218323f           // INV_T * log2(e)

#define TSTRIDE 272
#define TILEB   (128 * TSTRIDE)
#define SMEM_DYN (3 * TILEB)

__device__ __align__(16) __nv_bfloat16 g_Fbf[TWO_N * CDIM];
__device__ float g_sumpart[2 * TWO_N];
__device__ float g_pospart[2 * TWO_N];

__device__ __forceinline__ uint32_t smem_u32(const void* p) {
    uint32_t a;
    asm("{ .reg .u64 t; cvta.to.shared.u64 t, %1; cvt.u32.u64 %0, t; }"
        : "=r"(a) : "l"(p));
    return a;
}
__device__ __forceinline__ float ex2f(float x) {
    float r;
    asm("ex2.approx.ftz.f32 %0, %1;" : "=f"(r) : "f"(x));
    return r;
}
__device__ __forceinline__ void cp16(uint32_t s, const void* g) {
    asm volatile("cp.async.cg.shared.global [%0], [%1], 16;" :: "r"(s), "l"(g));
}
#define CP_COMMIT() asm volatile("cp.async.commit_group;" ::: "memory")
#define CP_WAIT1()  asm volatile("cp.async.wait_group 1;" ::: "memory")
#define CP_WAIT0()  asm volatile("cp.async.wait_group 0;" ::: "memory")

#define LDSM_X4(r0, r1, r2, r3, addr)                                          \
    asm volatile("ldmatrix.sync.aligned.m8n8.x4.shared.b16 {%0,%1,%2,%3},[%4];"\
        : "=r"(r0), "=r"(r1), "=r"(r2), "=r"(r3) : "r"(addr))

#define MMA16816(c, a, b0, b1)                                                 \
    asm volatile("mma.sync.aligned.m16n8k16.row.col.f32.bf16.bf16.f32 "        \
        "{%0,%1,%2,%3},{%4,%5,%6,%7},{%8,%9},{%0,%1,%2,%3};"                   \
        : "+f"((c)[0]), "+f"((c)[1]), "+f"((c)[2]), "+f"((c)[3])               \
        : "r"((a)[0]), "r"((a)[1]), "r"((a)[2]), "r"((a)[3]),                  \
          "r"(b0), "r"(b1))

// ---------------------------------------------------------------------------
// Kernel 1: L2-normalize + bf16 convert. 1 warp per row, 16 rows/block.
// ---------------------------------------------------------------------------
__global__ void __launch_bounds__(512) normalize_kernel(
        const float* __restrict__ f1, const float* __restrict__ f2) {
    int wid  = threadIdx.x >> 5;
    int lane = threadIdx.x & 31;
    int row  = blockIdx.x * 16 + wid;
    const float* src = (row < N_HALF) ? (f1 + (size_t)row * CDIM)
                                      : (f2 + (size_t)(row - N_HALF) * CDIM);
    float4 v = *(const float4*)(src + lane * 4);
    float s = v.x * v.x + v.y * v.y + v.z * v.z + v.w * v.w;
    #pragma unroll
    for (int o = 16; o; o >>= 1) s += __shfl_xor_sync(0xffffffffu, s, o);
    float inv = 1.0f / fmaxf(sqrtf(s), 1e-12f);
    __nv_bfloat162 p0 = __floats2bfloat162_rn(v.x * inv, v.y * inv);
    __nv_bfloat162 p1 = __floats2bfloat162_rn(v.z * inv, v.w * inv);
    uint2 u;
    u.x = *(uint32_t*)&p0;
    u.y = *(uint32_t*)&p1;
    *(uint2*)(g_Fbf + (size_t)row * CDIM + lane * 4) = u;
}

// ---------------------------------------------------------------------------
// Kernel 2: HMMA main. 64 rowblocks x 2 col halves = 128 CTAs, 8 warps each.
// Warp tile 64x32, mma m16n8k16. A resident, B double-buffered (cp.async).
// ---------------------------------------------------------------------------
extern __shared__ char dynsmem[];

__global__ void __launch_bounds__(256, 1) ntxent_mma_kernel() {
    const int tid  = threadIdx.x;
    const int lane = tid & 31;
    const int wid  = tid >> 5;
    const int wm   = wid & 1;        // warp row 0..1 (64 rows each)
    const int wn   = wid >> 1;       // warp col 0..3 (32 cols each)

    const int bx       = blockIdx.x;
    const int rowBase  = (bx >> 1) << 7;
    const int half     = bx & 1;
    const int colStart = half << 12;

    uint32_t sAu = smem_u32(dynsmem);
    uint32_t sBu[2] = { sAu + TILEB, sAu + 2 * TILEB };

    // Prologue: async-load A tile, B0, B1.
    {
        const char* gA  = (const char*)(g_Fbf + (size_t)rowBase * CDIM);
        const char* gB0 = (const char*)(g_Fbf + (size_t)colStart * CDIM);
        const char* gB1 = (const char*)(g_Fbf + (size_t)(colStart + 128) * CDIM);
        #pragma unroll
        for (int i = 0; i < 8; i++) {
            int idx = tid + i * 256, r = idx >> 4, c = idx & 15;
            cp16(sAu + r * TSTRIDE + c * 16, gA + r * 256 + c * 16);
            cp16(sBu[0] + r * TSTRIDE + c * 16, gB0 + r * 256 + c * 16);
        }
        CP_COMMIT();
        #pragma unroll
        for (int i = 0; i < 8; i++) {
            int idx = tid + i * 256, r = idx >> 4, c = idx & 15;
            cp16(sBu[1] + r * TSTRIDE + c * 16, gB1 + r * 256 + c * 16);
        }
        CP_COMMIT();
    }
    CP_WAIT1();
    __syncthreads();

    uint32_t aBase = sAu + (uint32_t)((wm * 64 + (lane & 15)) * TSTRIDE)
                         + (uint32_t)((lane >> 4) * 16);
    uint32_t bRowOff = (uint32_t)((wn * 32 + (lane & 7) + ((lane >> 4) & 1) * 8) * TSTRIDE)
                     + (uint32_t)(((lane >> 3) & 1) * 16);

    float rowAcc[8], posAcc[8];
    #pragma unroll
    for (int i = 0; i < 8; i++) { rowAcc[i] = 0.f; posAcc[i] = 0.f; }

    const int diagCb = ((rowBase >> 12) == half) ? ((rowBase - colStart) >> 7) : -1;
    const int pcBase = (rowBase + N_HALF) & (TWO_N - 1);
    const int posCb  = ((pcBase >> 12) == half) ? ((pcBase - colStart) >> 7) : -1;

    float accA[4][4][4], accB[4][4][4];

    // Rare-chunk fixups (diag exclusion / positive capture) on a finished acc.
    auto fixups = [&](float (&acc)[4][4][4], int cbv) {
        if (cbv == diagCb || cbv == posCb) {
            const bool isDiag = (cbv == diagCb);
            #pragma unroll
            for (int mi = 0; mi < 4; mi++)
                #pragma unroll
                for (int ni = 0; ni < 4; ni++)
                    #pragma unroll
                    for (int rg = 0; rg < 4; rg++) {
                        int rl = wm * 64 + mi * 16 + (lane >> 2) + 8 * (rg >> 1);
                        int cl = wn * 32 + ni * 8 + (lane & 3) * 2 + (rg & 1);
                        if (cl == rl) {
                            float f = acc[mi][ni][rg];
                            if (isDiag)
                                rowAcc[mi * 2 + (rg >> 1)] -= ex2f(fmaf(f, K1, -K1));
                            else
                                posAcc[mi * 2 + (rg >> 1)] += (f - 1.0f) * INV_T;
                        }
                    }
        }
    };

    // One chunk: K-loop into accC, epilogue of accP (chunk cb-1) interleaved.
    auto chunk_step = [&](float (&accC)[4][4][4], float (&accP)[4][4][4],
                          int cb, int doEpi) {
        const uint32_t sBc = sBu[cb & 1];
        #pragma unroll
        for (int mi = 0; mi < 4; mi++)
            #pragma unroll
            for (int ni = 0; ni < 4; ni++)
                #pragma unroll
                for (int rg = 0; rg < 4; rg++) accC[mi][ni][rg] = 0.f;

        #pragma unroll
        for (int ks = 0; ks < 8; ks++) {
            uint32_t afr[4][4], bfr[2][4];
            #pragma unroll
            for (int mi = 0; mi < 4; mi++) {
                uint32_t ad = aBase + (uint32_t)(mi * 16 * TSTRIDE + ks * 32);
                LDSM_X4(afr[mi][0], afr[mi][1], afr[mi][2], afr[mi][3], ad);
            }
            #pragma unroll
            for (int np = 0; np < 2; np++) {
                uint32_t bd = sBc + bRowOff + (uint32_t)(np * 16 * TSTRIDE + ks * 32);
                LDSM_X4(bfr[np][0], bfr[np][1], bfr[np][2], bfr[np][3], bd);
            }
            #pragma unroll
            for (int mi = 0; mi < 4; mi++)
                #pragma unroll
                for (int ni = 0; ni < 4; ni++)
                    MMA16816(accC[mi][ni], afr[mi],
                             bfr[ni >> 1][(ni & 1) * 2],
                             bfr[ni >> 1][(ni & 1) * 2 + 1]);

            if (doEpi) {   // 8 elements of accP per K-step -> 64 total
                #pragma unroll
                for (int j = 0; j < 8; j++) {
                    const int e  = ks * 8 + j;
                    const int mi = e >> 4, ni = (e >> 2) & 3, rg = e & 3;
                    rowAcc[mi * 2 + (rg >> 1)] +=
                        ex2f(fmaf(accP[mi][ni][rg], K1, -K1));
                }
            }
        }
        if (doEpi) fixups(accP, cb - 1);

        __syncthreads();                     // all warps done reading buf cb&1
        if (cb + 2 < 32) {
            const char* gB = (const char*)(g_Fbf +
                (size_t)(colStart + (cb + 2) * 128) * CDIM);
            #pragma unroll
            for (int i = 0; i < 8; i++) {
                int idx = tid + i * 256, r = idx >> 4, c = idx & 15;
                cp16(sBu[cb & 1] + r * TSTRIDE + c * 16, gB + r * 256 + c * 16);
            }
            CP_COMMIT();
        }
        if (cb + 1 < 32) {
            if (cb + 2 < 32) CP_WAIT1(); else CP_WAIT0();
            __syncthreads();
        }
    };

    chunk_step(accA, accB, 0, 0);            // chunk 0 -> accA
    for (int cb = 1; cb < 31; cb += 2) {
        chunk_step(accB, accA, cb, 1);       // odd  -> accB, epi chunk cb-1
        chunk_step(accA, accB, cb + 1, 1);   // even -> accA, epi chunk cb
    }
    chunk_step(accB, accA, 31, 1);           // chunk 31 -> accB, epi chunk 30

    // Tail epilogue: chunk 31.
    #pragma unroll
    for (int mi = 0; mi < 4; mi++)
        #pragma unroll
        for (int ni = 0; ni < 4; ni++)
            #pragma unroll
            for (int rg = 0; rg < 4; rg++)
                rowAcc[mi * 2 + (rg >> 1)] +=
                    ex2f(fmaf(accB[mi][ni][rg], K1, -K1));
    fixups(accB, 31);

    // Intra-warp: combine 4 lanes sharing each row.
    #pragma unroll
    for (int h = 0; h < 8; h++) {
        rowAcc[h] += __shfl_xor_sync(0xffffffffu, rowAcc[h], 1);
        rowAcc[h] += __shfl_xor_sync(0xffffffffu, rowAcc[h], 2);
        posAcc[h] += __shfl_xor_sync(0xffffffffu, posAcc[h], 1);
        posAcc[h] += __shfl_xor_sync(0xffffffffu, posAcc[h], 2);
    }
    __syncthreads();
    float* sRed = (float*)dynsmem;           // [128][4]
    float* sPos = (float*)dynsmem + 512;     // [128][4]
    if ((lane & 3) == 0) {
        #pragma unroll
        for (int h = 0; h < 8; h++) {
            int r = wm * 64 + (h >> 1) * 16 + (lane >> 2) + 8 * (h & 1);
            sRed[r * 4 + wn] = rowAcc[h];
            sPos[r * 4 + wn] = posAcc[h];
        }
    }
    __syncthreads();
    if (tid < 128) {
        float s = sRed[tid * 4] + sRed[tid * 4 + 1] + sRed[tid * 4 + 2] + sRed[tid * 4 + 3];
        float p = sPos[tid * 4] + sPos[tid * 4 + 1] + sPos[tid * 4 + 2] + sPos[tid * 4 + 3];
        g_sumpart[half * TWO_N + rowBase + tid] = s;
        g_pospart[half * TWO_N + rowBase + tid] = p;
    }
}

// ---------------------------------------------------------------------------
// Kernel 3: deterministic final reduction.
// ---------------------------------------------------------------------------
__global__ void __launch_bounds__(1024) reduce_kernel(float* __restrict__ out) {
    __shared__ double sm[1024];
    int t = threadIdx.x;
    double s = 0.0;
    for (int i = t; i < TWO_N; i += 1024) {
        float sum = g_sumpart[i] + g_sumpart[TWO_N + i];
        float pos = g_pospart[i] + g_pospart[TWO_N + i];
        s += (double)(pos - logf(sum));
    }
    sm[t] = s;
    __syncthreads();
    #pragma unroll
    for (int o = 512; o; o >>= 1) {
        if (t < o) sm[t] += sm[t + o];
        __syncthreads();
    }
    if (t == 0) out[0] = (float)(-sm[0] / (double)TWO_N);
}

// ---------------------------------------------------------------------------
extern "C" void kernel_launch(void* const* d_in, const int* in_sizes, int n_in,
                              void* d_out, int out_size) {
    const float* f1 = (const float*)d_in[0];
    const float* f2 = (const float*)d_in[1];
    float* out = (float*)d_out;

    cudaFuncSetAttribute(ntxent_mma_kernel,
                         cudaFuncAttributeMaxDynamicSharedMemorySize, SMEM_DYN);

    normalize_kernel<<<TWO_N / 16, 512>>>(f1, f2);
    ntxent_mma_kernel<<<128, 256, SMEM_DYN>>>();
    reduce_kernel<<<1, 1024>>>(out);
}

// round 5
// speedup vs baseline: 9.1939x; 1.0969x over previous
#include <cuda_runtime.h>
#include <cuda_bf16.h>
#include <math.h>
#include <stdint.h>

// NT-Xent, R5: exploit S = S^T. Only upper-triangle tiles (I<=J) of the 64x64
// tile grid are computed (2080 of 4096). Off-diag tile (I,J) produces row sums
// for block I (row-side) AND for block J (column sums of the same exp values).
// Persistent 148-CTA HMMA kernel, tiles strided by gridDim; cp.async double
// buffering of (A,B) tile pairs; prev-tile exp epilogue interleaved in K-loop.

#define TWO_N   8192
#define N_HALF  4096
#define CDIM    128
#define NBLK    64                           // 8192/128 row blocks
#define TILES   2080                         // 64*65/2
#define GRID    148
#define INV_T   14.285714285714286f          // 1/0.07
#define K1      20.60984248218323f           // INV_T * log2(e)

#define TSTRIDE 272
#define TILEB   (128 * TSTRIDE)
#define SMEM_DYN (4 * TILEB + 3072)

__device__ __align__(16) __nv_bfloat16 g_Fbf[TWO_N * CDIM];
__device__ float g_part[NBLK * NBLK * 128];  // [R][O][m] partial exp row sums
__device__ float g_pos[TWO_N];               // shifted positive logit per row
__device__ float g_rowlog[TWO_N];

__device__ __forceinline__ uint32_t smem_u32(const void* p) {
    uint32_t a;
    asm("{ .reg .u64 t; cvta.to.shared.u64 t, %1; cvt.u32.u64 %0, t; }"
        : "=r"(a) : "l"(p));
    return a;
}
__device__ __forceinline__ float ex2f(float x) {
    float r;
    asm("ex2.approx.ftz.f32 %0, %1;" : "=f"(r) : "f"(x));
    return r;
}
__device__ __forceinline__ void cp16(uint32_t s, const void* g) {
    asm volatile("cp.async.cg.shared.global [%0], [%1], 16;" :: "r"(s), "l"(g));
}
#define CP_COMMIT() asm volatile("cp.async.commit_group;" ::: "memory")
#define CP_WAIT1()  asm volatile("cp.async.wait_group 1;" ::: "memory")
#define CP_WAIT0()  asm volatile("cp.async.wait_group 0;" ::: "memory")

#define LDSM_X4(r0, r1, r2, r3, addr)                                          \
    asm volatile("ldmatrix.sync.aligned.m8n8.x4.shared.b16 {%0,%1,%2,%3},[%4];"\
        : "=r"(r0), "=r"(r1), "=r"(r2), "=r"(r3) : "r"(addr))

#define MMA16816(c, a, b0, b1)                                                 \
    asm volatile("mma.sync.aligned.m16n8k16.row.col.f32.bf16.bf16.f32 "        \
        "{%0,%1,%2,%3},{%4,%5,%6,%7},{%8,%9},{%0,%1,%2,%3};"                   \
        : "+f"((c)[0]), "+f"((c)[1]), "+f"((c)[2]), "+f"((c)[3])               \
        : "r"((a)[0]), "r"((a)[1]), "r"((a)[2]), "r"((a)[3]),                  \
          "r"(b0), "r"(b1))

// ---------------------------------------------------------------------------
// Kernel 1: L2-normalize + bf16 convert. 1 warp per row.
// ---------------------------------------------------------------------------
__global__ void __launch_bounds__(512) normalize_kernel(
        const float* __restrict__ f1, const float* __restrict__ f2) {
    int wid  = threadIdx.x >> 5;
    int lane = threadIdx.x & 31;
    int row  = blockIdx.x * 16 + wid;
    const float* src = (row < N_HALF) ? (f1 + (size_t)row * CDIM)
                                      : (f2 + (size_t)(row - N_HALF) * CDIM);
    float4 v = *(const float4*)(src + lane * 4);
    float s = v.x * v.x + v.y * v.y + v.z * v.z + v.w * v.w;
    #pragma unroll
    for (int o = 16; o; o >>= 1) s += __shfl_xor_sync(0xffffffffu, s, o);
    float inv = 1.0f / fmaxf(sqrtf(s), 1e-12f);
    __nv_bfloat162 p0 = __floats2bfloat162_rn(v.x * inv, v.y * inv);
    __nv_bfloat162 p1 = __floats2bfloat162_rn(v.z * inv, v.w * inv);
    uint2 u;
    u.x = *(uint32_t*)&p0;
    u.y = *(uint32_t*)&p1;
    *(uint2*)(g_Fbf + (size_t)row * CDIM + lane * 4) = u;
}

// ---------------------------------------------------------------------------
// Kernel 2: symmetric-triangle HMMA main.
// ---------------------------------------------------------------------------
extern __shared__ char dynsmem[];

__global__ void __launch_bounds__(256, 1) ntxent_mma_kernel() {
    const int tid  = threadIdx.x;
    const int lane = tid & 31;
    const int wid  = tid >> 5;
    const int wm   = wid & 1;
    const int wn   = wid >> 1;

    uint32_t sb = smem_u32(dynsmem);
    uint32_t bufA[2] = { sb,             sb + 2 * TILEB };
    uint32_t bufB[2] = { sb + TILEB,     sb + 3 * TILEB };
    float* sRow = (float*)(dynsmem + 4 * TILEB);   // [128][4]
    float* sCol = sRow + 512;                      // [128][2]

    const uint32_t aSel = (uint32_t)((wm * 64 + (lane & 15)) * TSTRIDE)
                        + (uint32_t)((lane >> 4) * 16);
    const uint32_t bSel = (uint32_t)((wn * 32 + (lane & 7) + ((lane >> 4) & 1) * 8) * TSTRIDE)
                        + (uint32_t)(((lane >> 3) & 1) * 16);

    auto mapIJ = [](int k, int& I, int& J) {
        int i = 0, rem = k;
        while (rem >= NBLK - i) { rem -= NBLK - i; i++; }
        I = i; J = i + rem;
    };
    auto issue_tile = [&](int I, int J, int buf) {
        const char* gA = (const char*)(g_Fbf + ((size_t)I << 7) * CDIM);
        const char* gB = (const char*)(g_Fbf + ((size_t)J << 7) * CDIM);
        #pragma unroll
        for (int i = 0; i < 8; i++) {
            int idx = tid + i * 256, r = idx >> 4, c = idx & 15;
            cp16(bufA[buf] + r * TSTRIDE + c * 16, gA + r * 256 + c * 16);
            cp16(bufB[buf] + r * TSTRIDE + c * 16, gB + r * 256 + c * 16);
        }
        CP_COMMIT();
    };

    float accA[4][4][4], accB[4][4][4];
    float rA[8], cA[8], rB[8], cB[8];
    #pragma unroll
    for (int i = 0; i < 8; i++) { rA[i] = cA[i] = rB[i] = cB[i] = 0.f; }

    // K-loop on buf cur; optional interleaved exp epilogue of accP.
    auto kloop = [&](float (&accC)[4][4][4], float (&accP)[4][4][4],
                     float (&pr)[8], float (&pc)[8], int cur, int doEpi) {
        const uint32_t aT = bufA[cur] + aSel;
        const uint32_t bT = bufB[cur] + bSel;
        #pragma unroll
        for (int mi = 0; mi < 4; mi++)
            #pragma unroll
            for (int ni = 0; ni < 4; ni++)
                #pragma unroll
                for (int rg = 0; rg < 4; rg++) accC[mi][ni][rg] = 0.f;
        #pragma unroll
        for (int ks = 0; ks < 8; ks++) {
            uint32_t afr[4][4], bfr[2][4];
            #pragma unroll
            for (int mi = 0; mi < 4; mi++) {
                uint32_t ad = aT + (uint32_t)(mi * 16 * TSTRIDE + ks * 32);
                LDSM_X4(afr[mi][0], afr[mi][1], afr[mi][2], afr[mi][3], ad);
            }
            #pragma unroll
            for (int np = 0; np < 2; np++) {
                uint32_t bd = bT + (uint32_t)(np * 16 * TSTRIDE + ks * 32);
                LDSM_X4(bfr[np][0], bfr[np][1], bfr[np][2], bfr[np][3], bd);
            }
            #pragma unroll
            for (int mi = 0; mi < 4; mi++)
                #pragma unroll
                for (int ni = 0; ni < 4; ni++)
                    MMA16816(accC[mi][ni], afr[mi],
                             bfr[ni >> 1][(ni & 1) * 2],
                             bfr[ni >> 1][(ni & 1) * 2 + 1]);
            if (doEpi) {
                #pragma unroll
                for (int j = 0; j < 8; j++) {
                    const int e  = ks * 8 + j;
                    const int mi = e >> 4, ni = (e >> 2) & 3, rg = e & 3;
                    float ex = ex2f(fmaf(accP[mi][ni][rg], K1, -K1));
                    pr[mi * 2 + (rg >> 1)] += ex;
                    pc[ni * 2 + (rg & 1)]  += ex;
                }
            }
        }
    };

    // Serial epilogue (flush path).
    auto epi_all = [&](float (&acc)[4][4][4], float (&pr)[8], float (&pc)[8]) {
        #pragma unroll
        for (int mi = 0; mi < 4; mi++)
            #pragma unroll
            for (int ni = 0; ni < 4; ni++)
                #pragma unroll
                for (int rg = 0; rg < 4; rg++) {
                    float ex = ex2f(fmaf(acc[mi][ni][rg], K1, -K1));
                    pr[mi * 2 + (rg >> 1)] += ex;
                    pc[ni * 2 + (rg & 1)]  += ex;
                }
    };

    // Fixups + block reduce + writeout for a finished tile (pI,pJ); zeroes pr/pc.
    auto finish = [&](float (&acc)[4][4][4], float (&pr)[8], float (&pc)[8],
                      int pI, int pJ) {
        const bool isDiag = (pI == pJ);
        const bool isPos  = (pJ == pI + 32);
        if (isDiag || isPos) {
            #pragma unroll
            for (int mi = 0; mi < 4; mi++)
                #pragma unroll
                for (int ni = 0; ni < 4; ni++)
                    #pragma unroll
                    for (int rg = 0; rg < 4; rg++) {
                        int rl = wm * 64 + mi * 16 + (lane >> 2) + 8 * (rg >> 1);
                        int cl = wn * 32 + ni * 8 + (lane & 3) * 2 + (rg & 1);
                        if (cl == rl) {
                            float f = acc[mi][ni][rg];
                            if (isDiag) {
                                pr[mi * 2 + (rg >> 1)] -= ex2f(fmaf(f, K1, -K1));
                            } else {
                                float v = (f - 1.0f) * INV_T;
                                g_pos[pI * 128 + rl] = v;   // row i
                                g_pos[pJ * 128 + cl] = v;   // partner row j
                            }
                        }
                    }
        }
        // Row reduce: sum over lane&3 (columns within quad).
        #pragma unroll
        for (int h = 0; h < 8; h++) {
            pr[h] += __shfl_xor_sync(0xffffffffu, pr[h], 1);
            pr[h] += __shfl_xor_sync(0xffffffffu, pr[h], 2);
            pc[h] += __shfl_xor_sync(0xffffffffu, pc[h], 4);
            pc[h] += __shfl_xor_sync(0xffffffffu, pc[h], 8);
            pc[h] += __shfl_xor_sync(0xffffffffu, pc[h], 16);
        }
        if ((lane & 3) == 0) {
            #pragma unroll
            for (int h = 0; h < 8; h++) {
                int r = wm * 64 + (h >> 1) * 16 + (lane >> 2) + 8 * (h & 1);
                sRow[r * 4 + wn] = pr[h];
            }
        }
        if (lane < 4) {
            #pragma unroll
            for (int h = 0; h < 8; h++) {
                int col = wn * 32 + (h >> 1) * 8 + lane * 2 + (h & 1);
                sCol[col * 2 + wm] = pc[h];
            }
        }
        __syncthreads();
        if (tid < 128) {
            float rs = sRow[tid * 4] + sRow[tid * 4 + 1]
                     + sRow[tid * 4 + 2] + sRow[tid * 4 + 3];
            g_part[((size_t)pI * NBLK + pJ) * 128 + tid] = rs;
            if (!isDiag) {
                float cs = sCol[tid * 2] + sCol[tid * 2 + 1];
                g_part[((size_t)pJ * NBLK + pI) * 128 + tid] = cs;
            }
        }
        #pragma unroll
        for (int h = 0; h < 8; h++) { pr[h] = 0.f; pc[h] = 0.f; }
    };

    // ---- tile pipeline ----
    int k0 = blockIdx.x;
    int I, J, In, Jn, prevI, prevJ;
    mapIJ(k0, I, J);
    issue_tile(I, J, 0);

    int k1 = k0 + GRID;
    bool hn = (k1 < TILES);
    if (hn) { mapIJ(k1, In, Jn); issue_tile(In, Jn, 1); CP_WAIT1(); }
    else    { CP_WAIT0(); }
    __syncthreads();

    kloop(accA, accB, rB, cB, 0, 0);          // tile 0 -> accA
    prevI = I; prevJ = J;
    __syncthreads();                          // buf0 reads done before reuse

    int t = 1;
    for (int k = k1; k < TILES; k += GRID, t++) {
        I = In; J = Jn;
        int cur = t & 1;
        int kn = k + GRID;
        hn = (kn < TILES);
        if (hn) { mapIJ(kn, In, Jn); issue_tile(In, Jn, 1 - cur); }
        if (hn) CP_WAIT1(); else CP_WAIT0();
        __syncthreads();

        if (t & 1) {
            kloop(accB, accA, rA, cA, cur, 1);
            finish(accA, rA, cA, prevI, prevJ);
        } else {
            kloop(accA, accB, rB, cB, cur, 1);
            finish(accB, rB, cB, prevI, prevJ);
        }
        prevI = I; prevJ = J;
        __syncthreads();                      // buf cur reads done before reuse
    }

    // Flush last tile (t-1 parity decides which acc holds it).
    if ((t - 1) & 1) { epi_all(accB, rB, cB); finish(accB, rB, cB, prevI, prevJ); }
    else             { epi_all(accA, rA, cA); finish(accA, rA, cA, prevI, prevJ); }
}

// ---------------------------------------------------------------------------
// Kernel 3: per-row gather of 64 partials -> log_prob.
// ---------------------------------------------------------------------------
__global__ void __launch_bounds__(256) reduce1_kernel() {
    int row = blockIdx.x * 256 + threadIdx.x;
    int R = row >> 7, m = row & 127;
    float s = 0.f;
    #pragma unroll 8
    for (int O = 0; O < NBLK; O++)
        s += g_part[((size_t)R * NBLK + O) * 128 + m];
    g_rowlog[row] = g_pos[row] - logf(s);
}

// ---------------------------------------------------------------------------
// Kernel 4: deterministic final mean.
// ---------------------------------------------------------------------------
__global__ void __launch_bounds__(1024) reduce2_kernel(float* __restrict__ out) {
    __shared__ double sm[1024];
    int tI = threadIdx.x;
    double s = 0.0;
    for (int i = tI; i < TWO_N; i += 1024) s += (double)g_rowlog[i];
    sm[tI] = s;
    __syncthreads();
    #pragma unroll
    for (int o = 512; o; o >>= 1) {
        if (tI < o) sm[tI] += sm[tI + o];
        __syncthreads();
    }
    if (tI == 0) out[0] = (float)(-sm[0] / (double)TWO_N);
}

// ---------------------------------------------------------------------------
extern "C" void kernel_launch(void* const* d_in, const int* in_sizes, int n_in,
                              void* d_out, int out_size) {
    const float* f1 = (const float*)d_in[0];
    const float* f2 = (const float*)d_in[1];
    float* out = (float*)d_out;

    cudaFuncSetAttribute(ntxent_mma_kernel,
                         cudaFuncAttributeMaxDynamicSharedMemorySize, SMEM_DYN);

    normalize_kernel<<<TWO_N / 16, 512>>>(f1, f2);
    ntxent_mma_kernel<<<GRID, 256, SMEM_DYN>>>();
    reduce1_kernel<<<TWO_N / 256, 256>>>();
    reduce2_kernel<<<1, 1024>>>(out);
}

// round 6
// speedup vs baseline: 10.1374x; 1.1026x over previous
#include <cuda_runtime.h>
#include <cuda_fp16.h>
#include <math.h>
#include <stdint.h>

// NT-Xent R6: fp16 HMMA (f16 accumulate, 2x legacy rate on sm_103a),
// symmetric upper-triangle tiles, exact fp32 positive-pair logits computed in
// the normalize kernel, interleaved exp epilogue, cheap two-stage reduction.

#define TWO_N   8192
#define N_HALF  4096
#define CDIM    128
#define NBLK    64
#define TILES   2080                         // 64*65/2
#define GRID    148
#define INV_T   14.285714285714286f          // 1/0.07
#define K1      20.60984248218323f           // INV_T * log2(e)

#define TSTRIDE 272
#define TILEB   (128 * TSTRIDE)
#define SMEM_DYN (4 * TILEB + 3072)

__device__ __align__(16) __half g_Fh[TWO_N * CDIM];
__device__ float g_part[NBLK * NBLK * 128];  // [R][O][m] partial exp row sums
__device__ float g_pos[TWO_N];               // exact fp32 positive logit (shifted)
__device__ double g_bsum[32];

__device__ __forceinline__ uint32_t smem_u32(const void* p) {
    uint32_t a;
    asm("{ .reg .u64 t; cvta.to.shared.u64 t, %1; cvt.u32.u64 %0, t; }"
        : "=r"(a) : "l"(p));
    return a;
}
__device__ __forceinline__ float ex2f(float x) {
    float r;
    asm("ex2.approx.ftz.f32 %0, %1;" : "=f"(r) : "f"(x));
    return r;
}
__device__ __forceinline__ void cp16(uint32_t s, const void* g) {
    asm volatile("cp.async.cg.shared.global [%0], [%1], 16;" :: "r"(s), "l"(g));
}
#define CP_COMMIT() asm volatile("cp.async.commit_group;" ::: "memory")
#define CP_WAIT1()  asm volatile("cp.async.wait_group 1;" ::: "memory")
#define CP_WAIT0()  asm volatile("cp.async.wait_group 0;" ::: "memory")

#define LDSM_X4(r0, r1, r2, r3, addr)                                          \
    asm volatile("ldmatrix.sync.aligned.m8n8.x4.shared.b16 {%0,%1,%2,%3},[%4];"\
        : "=r"(r0), "=r"(r1), "=r"(r2), "=r"(r3) : "r"(addr))

// f16 accumulate: D,C packed half2 x2
#define MMA16816H(c, a, b0, b1)                                                \
    asm volatile("mma.sync.aligned.m16n8k16.row.col.f16.f16.f16.f16 "          \
        "{%0,%1},{%2,%3,%4,%5},{%6,%7},{%0,%1};"                               \
        : "+r"((c)[0]), "+r"((c)[1])                                           \
        : "r"((a)[0]), "r"((a)[1]), "r"((a)[2]), "r"((a)[3]),                  \
          "r"(b0), "r"(b1))

// ---------------------------------------------------------------------------
// Kernel 1: normalize both halves (fp16 out) + exact fp32 positive logits.
// One warp per pair i: rows i (f1) and i+N (f2).
// ---------------------------------------------------------------------------
__global__ void __launch_bounds__(256) normalize_kernel(
        const float* __restrict__ f1, const float* __restrict__ f2) {
    int wid  = threadIdx.x >> 5;
    int lane = threadIdx.x & 31;
    int i    = blockIdx.x * 8 + wid;

    float4 a = *(const float4*)(f1 + (size_t)i * CDIM + lane * 4);
    float4 b = *(const float4*)(f2 + (size_t)i * CDIM + lane * 4);
    float s1 = a.x * a.x + a.y * a.y + a.z * a.z + a.w * a.w;
    float s2 = b.x * b.x + b.y * b.y + b.z * b.z + b.w * b.w;
    float d  = a.x * b.x + a.y * b.y + a.z * b.z + a.w * b.w;
    #pragma unroll
    for (int o = 16; o; o >>= 1) {
        s1 += __shfl_xor_sync(0xffffffffu, s1, o);
        s2 += __shfl_xor_sync(0xffffffffu, s2, o);
        d  += __shfl_xor_sync(0xffffffffu, d,  o);
    }
    float n1 = fmaxf(sqrtf(s1), 1e-12f);
    float n2 = fmaxf(sqrtf(s2), 1e-12f);
    float i1 = 1.0f / n1, i2 = 1.0f / n2;

    __half2 h0 = __floats2half2_rn(a.x * i1, a.y * i1);
    __half2 h1 = __floats2half2_rn(a.z * i1, a.w * i1);
    uint2 u;
    u.x = *(uint32_t*)&h0; u.y = *(uint32_t*)&h1;
    *(uint2*)(g_Fh + (size_t)i * CDIM + lane * 4) = u;

    __half2 g0 = __floats2half2_rn(b.x * i2, b.y * i2);
    __half2 g1 = __floats2half2_rn(b.z * i2, b.w * i2);
    u.x = *(uint32_t*)&g0; u.y = *(uint32_t*)&g1;
    *(uint2*)(g_Fh + (size_t)(i + N_HALF) * CDIM + lane * 4) = u;

    if (lane == 0) {
        float pos = (d * i1 * i2 - 1.0f) * INV_T;   // exact shifted pos logit
        g_pos[i] = pos;
        g_pos[i + N_HALF] = pos;
    }
}

// ---------------------------------------------------------------------------
// Kernel 2: symmetric-triangle fp16 HMMA main.
// ---------------------------------------------------------------------------
extern __shared__ char dynsmem[];

__global__ void __launch_bounds__(256, 1) ntxent_mma_kernel() {
    const int tid  = threadIdx.x;
    const int lane = tid & 31;
    const int wid  = tid >> 5;
    const int wm   = wid & 1;
    const int wn   = wid >> 1;

    uint32_t sb = smem_u32(dynsmem);
    uint32_t bufA[2] = { sb,         sb + 2 * TILEB };
    uint32_t bufB[2] = { sb + TILEB, sb + 3 * TILEB };
    float* sRow = (float*)(dynsmem + 4 * TILEB);   // [128][4]
    float* sCol = sRow + 512;                      // [128][2]

    const uint32_t aSel = (uint32_t)((wm * 64 + (lane & 15)) * TSTRIDE)
                        + (uint32_t)((lane >> 4) * 16);
    const uint32_t bSel = (uint32_t)((wn * 32 + (lane & 7) + ((lane >> 4) & 1) * 8) * TSTRIDE)
                        + (uint32_t)(((lane >> 3) & 1) * 16);

    auto mapIJ = [](int k, int& I, int& J) {
        int i = 0, rem = k;
        while (rem >= NBLK - i) { rem -= NBLK - i; i++; }
        I = i; J = i + rem;
    };
    auto issue_tile = [&](int I, int J, int buf) {
        const char* gA = (const char*)(g_Fh + ((size_t)I << 7) * CDIM);
        const char* gB = (const char*)(g_Fh + ((size_t)J << 7) * CDIM);
        #pragma unroll
        for (int i = 0; i < 8; i++) {
            int idx = tid + i * 256, r = idx >> 4, c = idx & 15;
            cp16(bufA[buf] + r * TSTRIDE + c * 16, gA + r * 256 + c * 16);
            cp16(bufB[buf] + r * TSTRIDE + c * 16, gB + r * 256 + c * 16);
        }
        CP_COMMIT();
    };

    // acc[mi][ni][rg]: rg=0 rows (lane>>2), rg=1 rows +8; each packs 2 cols.
    uint32_t accA[4][4][2], accB[4][4][2];
    float rA[8], cA[8], rB[8], cB[8];
    #pragma unroll
    for (int i = 0; i < 8; i++) { rA[i] = cA[i] = rB[i] = cB[i] = 0.f; }

    // Epilogue for one packed reg e (0..31): rows h=mi*2+rg, cols ni*2+{0,1}.
    auto epi_reg = [&](uint32_t v, int e, float (&pr)[8], float (&pc)[8]) {
        const int mi = e >> 3, ni = (e >> 1) & 3, rg = e & 1;
        float2 f = __half22float2(*(const __half2*)&v);
        float e0 = ex2f(fmaf(f.x, K1, -K1));
        float e1 = ex2f(fmaf(f.y, K1, -K1));
        pr[mi * 2 + rg] += e0 + e1;
        pc[ni * 2]     += e0;
        pc[ni * 2 + 1] += e1;
    };

    auto kloop = [&](uint32_t (&accC)[4][4][2], uint32_t (&accP)[4][4][2],
                     float (&pr)[8], float (&pc)[8], int cur, int doEpi) {
        const uint32_t aT = bufA[cur] + aSel;
        const uint32_t bT = bufB[cur] + bSel;
        #pragma unroll
        for (int mi = 0; mi < 4; mi++)
            #pragma unroll
            for (int ni = 0; ni < 4; ni++) {
                accC[mi][ni][0] = 0u; accC[mi][ni][1] = 0u;
            }
        #pragma unroll
        for (int ks = 0; ks < 8; ks++) {
            uint32_t afr[4][4], bfr[2][4];
            #pragma unroll
            for (int mi = 0; mi < 4; mi++) {
                uint32_t ad = aT + (uint32_t)(mi * 16 * TSTRIDE + ks * 32);
                LDSM_X4(afr[mi][0], afr[mi][1], afr[mi][2], afr[mi][3], ad);
            }
            #pragma unroll
            for (int np = 0; np < 2; np++) {
                uint32_t bd = bT + (uint32_t)(np * 16 * TSTRIDE + ks * 32);
                LDSM_X4(bfr[np][0], bfr[np][1], bfr[np][2], bfr[np][3], bd);
            }
            #pragma unroll
            for (int mi = 0; mi < 4; mi++)
                #pragma unroll
                for (int ni = 0; ni < 4; ni++)
                    MMA16816H(accC[mi][ni], afr[mi],
                              bfr[ni >> 1][(ni & 1) * 2],
                              bfr[ni >> 1][(ni & 1) * 2 + 1]);
            if (doEpi) {
                #pragma unroll
                for (int j = 0; j < 4; j++) {
                    const int e = ks * 4 + j;
                    epi_reg(accP[e >> 3][(e >> 1) & 3][e & 1], e, pr, pc);
                }
            }
        }
    };

    auto epi_all = [&](uint32_t (&acc)[4][4][2], float (&pr)[8], float (&pc)[8]) {
        #pragma unroll
        for (int e = 0; e < 32; e++)
            epi_reg(acc[e >> 3][(e >> 1) & 3][e & 1], e, pr, pc);
    };

    auto finish = [&](uint32_t (&acc)[4][4][2], float (&pr)[8], float (&pc)[8],
                      int pI, int pJ) {
        const bool isDiag = (pI == pJ);
        if (isDiag) {
            #pragma unroll
            for (int mi = 0; mi < 4; mi++)
                #pragma unroll
                for (int ni = 0; ni < 4; ni++)
                    #pragma unroll
                    for (int rg = 0; rg < 2; rg++) {
                        int rl = wm * 64 + mi * 16 + (lane >> 2) + 8 * rg;
                        int c0 = wn * 32 + ni * 8 + (lane & 3) * 2;
                        if (c0 == rl || c0 + 1 == rl) {
                            float2 f = __half22float2(
                                *(const __half2*)&acc[mi][ni][rg]);
                            float fd = (c0 == rl) ? f.x : f.y;
                            pr[mi * 2 + rg] -= ex2f(fmaf(fd, K1, -K1));
                        }
                    }
        }
        #pragma unroll
        for (int h = 0; h < 8; h++) {
            pr[h] += __shfl_xor_sync(0xffffffffu, pr[h], 1);
            pr[h] += __shfl_xor_sync(0xffffffffu, pr[h], 2);
            pc[h] += __shfl_xor_sync(0xffffffffu, pc[h], 4);
            pc[h] += __shfl_xor_sync(0xffffffffu, pc[h], 8);
            pc[h] += __shfl_xor_sync(0xffffffffu, pc[h], 16);
        }
        if ((lane & 3) == 0) {
            #pragma unroll
            for (int h = 0; h < 8; h++) {
                int r = wm * 64 + (h >> 1) * 16 + (lane >> 2) + 8 * (h & 1);
                sRow[r * 4 + wn] = pr[h];
            }
        }
        if (lane < 4) {
            #pragma unroll
            for (int h = 0; h < 8; h++) {
                int col = wn * 32 + (h >> 1) * 8 + lane * 2 + (h & 1);
                sCol[col * 2 + wm] = pc[h];
            }
        }
        __syncthreads();
        if (tid < 128) {
            float rs = sRow[tid * 4] + sRow[tid * 4 + 1]
                     + sRow[tid * 4 + 2] + sRow[tid * 4 + 3];
            g_part[((size_t)pI * NBLK + pJ) * 128 + tid] = rs;
            if (!isDiag) {
                float cs = sCol[tid * 2] + sCol[tid * 2 + 1];
                g_part[((size_t)pJ * NBLK + pI) * 128 + tid] = cs;
            }
        }
        #pragma unroll
        for (int h = 0; h < 8; h++) { pr[h] = 0.f; pc[h] = 0.f; }
    };

    // ---- tile pipeline ----
    int k0 = blockIdx.x;
    int I, J, In, Jn, prevI, prevJ;
    mapIJ(k0, I, J);
    issue_tile(I, J, 0);

    int k1 = k0 + GRID;
    bool hn = (k1 < TILES);
    if (hn) { mapIJ(k1, In, Jn); issue_tile(In, Jn, 1); CP_WAIT1(); }
    else    { CP_WAIT0(); }
    __syncthreads();

    kloop(accA, accB, rB, cB, 0, 0);
    prevI = I; prevJ = J;
    __syncthreads();

    int t = 1;
    for (int k = k1; k < TILES; k += GRID, t++) {
        I = In; J = Jn;
        int cur = t & 1;
        int kn = k + GRID;
        hn = (kn < TILES);
        if (hn) { mapIJ(kn, In, Jn); issue_tile(In, Jn, 1 - cur); }
        if (hn) CP_WAIT1(); else CP_WAIT0();
        __syncthreads();

        if (t & 1) {
            kloop(accB, accA, rA, cA, cur, 1);
            finish(accA, rA, cA, prevI, prevJ);
        } else {
            kloop(accA, accB, rB, cB, cur, 1);
            finish(accB, rB, cB, prevI, prevJ);
        }
        prevI = I; prevJ = J;
        __syncthreads();
    }

    if ((t - 1) & 1) { epi_all(accB, rB, cB); finish(accB, rB, cB, prevI, prevJ); }
    else             { epi_all(accA, rA, cA); finish(accA, rA, cA, prevI, prevJ); }
}

// ---------------------------------------------------------------------------
// Kernel 3: per-row gather -> log_prob, plus per-block double partial sums.
// ---------------------------------------------------------------------------
__global__ void __launch_bounds__(256) reduce1_kernel() {
    __shared__ double sm[256];
    int tid = threadIdx.x;
    int row = blockIdx.x * 256 + tid;
    int R = row >> 7, m = row & 127;
    float s = 0.f;
    #pragma unroll 8
    for (int O = 0; O < NBLK; O++)
        s += g_part[((size_t)R * NBLK + O) * 128 + m];
    sm[tid] = (double)(g_pos[row] - logf(s));
    __syncthreads();
    #pragma unroll
    for (int o = 128; o; o >>= 1) {
        if (tid < o) sm[tid] += sm[tid + o];
        __syncthreads();
    }
    if (tid == 0) g_bsum[blockIdx.x] = sm[0];
}

// ---------------------------------------------------------------------------
// Kernel 4: sum 32 block partials -> loss.
// ---------------------------------------------------------------------------
__global__ void reduce2_kernel(float* __restrict__ out) {
    int t = threadIdx.x;
    double s = g_bsum[t];
    #pragma unroll
    for (int o = 16; o; o >>= 1) s += __shfl_xor_sync(0xffffffffu, s, o);
    if (t == 0) out[0] = (float)(-s / (double)TWO_N);
}

// ---------------------------------------------------------------------------
extern "C" void kernel_launch(void* const* d_in, const int* in_sizes, int n_in,
                              void* d_out, int out_size) {
    const float* f1 = (const float*)d_in[0];
    const float* f2 = (const float*)d_in[1];
    float* out = (float*)d_out;

    cudaFuncSetAttribute(ntxent_mma_kernel,
                         cudaFuncAttributeMaxDynamicSharedMemorySize, SMEM_DYN);

    normalize_kernel<<<N_HALF / 8, 256>>>(f1, f2);
    ntxent_mma_kernel<<<GRID, 256, SMEM_DYN>>>();
    reduce1_kernel<<<TWO_N / 256, 256>>>();
    reduce2_kernel<<<1, 32>>>(out);
}

// round 7
// speedup vs baseline: 10.6079x; 1.0464x over previous
#include <cuda_runtime.h>
#include <cuda_fp16.h>
#include <math.h>
#include <stdint.h>

// NT-Xent R7: 512-thread CTAs (4 warps/SMSP) for latency hiding, CTA tile
// 128x256 over the upper triangle at 256-col granularity (1056 tiles),
// single fp16 accumulator (<=128 regs), serial exp epilogue, fused final
// reduction (threadfence + counter, deterministic).

#define TWO_N   8192
#define N_HALF  4096
#define CDIM    128
#define NBLK    64
#define TILES   1056                         // sum_I (32 - I/2)
#define GRID    148
#define INV_T   14.285714285714286f
#define K1      20.60984248218323f           // INV_T * log2(e)

#define TSTRIDE 272
#define A_BYTES (128 * TSTRIDE)              // 34816
#define B_BYTES (256 * TSTRIDE)              // 69632
#define OFF_A0  0
#define OFF_A1  A_BYTES
#define OFF_B0  (2 * A_BYTES)
#define OFF_B1  (2 * A_BYTES + B_BYTES)
#define OFF_RED (2 * A_BYTES + 2 * B_BYTES)  // 208896
#define SMEM_DYN (OFF_RED + 128 * 9 * 4 + 256 * 2 * 4)   // 215552

__device__ __align__(16) __half g_Fh[TWO_N * CDIM];
__device__ float g_part[NBLK * NBLK * 128];
__device__ float g_pos[TWO_N];
__device__ double g_bsum[32];
__device__ int g_ctr;

__device__ __forceinline__ uint32_t smem_u32(const void* p) {
    uint32_t a;
    asm("{ .reg .u64 t; cvta.to.shared.u64 t, %1; cvt.u32.u64 %0, t; }"
        : "=r"(a) : "l"(p));
    return a;
}
__device__ __forceinline__ float ex2f(float x) {
    float r;
    asm("ex2.approx.ftz.f32 %0, %1;" : "=f"(r) : "f"(x));
    return r;
}
__device__ __forceinline__ void cp16(uint32_t s, const void* g) {
    asm volatile("cp.async.cg.shared.global [%0], [%1], 16;" :: "r"(s), "l"(g));
}
#define CP_COMMIT() asm volatile("cp.async.commit_group;" ::: "memory")
#define CP_WAIT1()  asm volatile("cp.async.wait_group 1;" ::: "memory")
#define CP_WAIT0()  asm volatile("cp.async.wait_group 0;" ::: "memory")

#define LDSM_X4(r0, r1, r2, r3, addr)                                          \
    asm volatile("ldmatrix.sync.aligned.m8n8.x4.shared.b16 {%0,%1,%2,%3},[%4];"\
        : "=r"(r0), "=r"(r1), "=r"(r2), "=r"(r3) : "r"(addr))

#define MMA16816H(c, a, b0, b1)                                                \
    asm volatile("mma.sync.aligned.m16n8k16.row.col.f16.f16.f16.f16 "          \
        "{%0,%1},{%2,%3,%4,%5},{%6,%7},{%0,%1};"                               \
        : "+r"((c)[0]), "+r"((c)[1])                                           \
        : "r"((a)[0]), "r"((a)[1]), "r"((a)[2]), "r"((a)[3]),                  \
          "r"(b0), "r"(b1))

// ---------------------------------------------------------------------------
// Kernel 1: normalize both halves (fp16) + exact fp32 positive logits.
// ---------------------------------------------------------------------------
__global__ void __launch_bounds__(256) normalize_kernel(
        const float* __restrict__ f1, const float* __restrict__ f2) {
    int wid  = threadIdx.x >> 5;
    int lane = threadIdx.x & 31;
    int i    = blockIdx.x * 8 + wid;

    float4 a = *(const float4*)(f1 + (size_t)i * CDIM + lane * 4);
    float4 b = *(const float4*)(f2 + (size_t)i * CDIM + lane * 4);
    float s1 = a.x * a.x + a.y * a.y + a.z * a.z + a.w * a.w;
    float s2 = b.x * b.x + b.y * b.y + b.z * b.z + b.w * b.w;
    float d  = a.x * b.x + a.y * b.y + a.z * b.z + a.w * b.w;
    #pragma unroll
    for (int o = 16; o; o >>= 1) {
        s1 += __shfl_xor_sync(0xffffffffu, s1, o);
        s2 += __shfl_xor_sync(0xffffffffu, s2, o);
        d  += __shfl_xor_sync(0xffffffffu, d,  o);
    }
    float i1 = 1.0f / fmaxf(sqrtf(s1), 1e-12f);
    float i2 = 1.0f / fmaxf(sqrtf(s2), 1e-12f);

    __half2 h0 = __floats2half2_rn(a.x * i1, a.y * i1);
    __half2 h1 = __floats2half2_rn(a.z * i1, a.w * i1);
    uint2 u;
    u.x = *(uint32_t*)&h0; u.y = *(uint32_t*)&h1;
    *(uint2*)(g_Fh + (size_t)i * CDIM + lane * 4) = u;

    __half2 g0 = __floats2half2_rn(b.x * i2, b.y * i2);
    __half2 g1 = __floats2half2_rn(b.z * i2, b.w * i2);
    u.x = *(uint32_t*)&g0; u.y = *(uint32_t*)&g1;
    *(uint2*)(g_Fh + (size_t)(i + N_HALF) * CDIM + lane * 4) = u;

    if (lane == 0) {
        float pos = (d * i1 * i2 - 1.0f) * INV_T;
        g_pos[i] = pos;
        g_pos[i + N_HALF] = pos;
    }
}

// ---------------------------------------------------------------------------
// Kernel 2: main. 148 persistent CTAs x 512 threads. CTA tile 128x256.
// Warp (wm=wid&1, wn=wid>>1): rows wm*64..+64, cols wn*32..+32 of tile.
// J-block of warp = 2*J2 + (wn>>2). Inactive if Jblk < I.
// ---------------------------------------------------------------------------
extern __shared__ char dynsmem[];

__global__ void __launch_bounds__(512, 1) ntxent_mma_kernel() {
    const int tid  = threadIdx.x;
    const int lane = tid & 31;
    const int wid  = tid >> 5;
    const int wm   = wid & 1;
    const int wn   = wid >> 1;       // 0..7

    uint32_t sb = smem_u32(dynsmem);
    const uint32_t bufA[2] = { sb + OFF_A0, sb + OFF_A1 };
    const uint32_t bufB[2] = { sb + OFF_B0, sb + OFF_B1 };
    float* sRow = (float*)(dynsmem + OFF_RED);       // [128][9]
    float* sCol = sRow + 128 * 9;                    // [256][2]

    const uint32_t aSel = (uint32_t)((wm * 64 + (lane & 15)) * TSTRIDE)
                        + (uint32_t)((lane >> 4) * 16);
    const uint32_t bSel = (uint32_t)((wn * 32 + (lane & 7) + ((lane >> 4) & 1) * 8) * TSTRIDE)
                        + (uint32_t)(((lane >> 3) & 1) * 16);

    auto mapIJ = [](int k, int& I, int& J2) {
        int i = 0, rem = k;
        while (rem >= 32 - (i >> 1)) { rem -= 32 - (i >> 1); i++; }
        I = i; J2 = (i >> 1) + rem;
    };
    auto issue_tile = [&](int I, int J2, int buf) {
        const char* gA = (const char*)(g_Fh + ((size_t)I << 7) * CDIM);
        const char* gB = (const char*)(g_Fh + ((size_t)J2 << 8) * CDIM);
        #pragma unroll
        for (int i = 0; i < 4; i++) {
            int idx = tid + i * 512, r = idx >> 4, c = idx & 15;
            cp16(bufA[buf] + r * TSTRIDE + c * 16, gA + r * 256 + c * 16);
        }
        #pragma unroll
        for (int i = 0; i < 8; i++) {
            int idx = tid + i * 512, r = idx >> 4, c = idx & 15;
            cp16(bufB[buf] + r * TSTRIDE + c * 16, gB + r * 256 + c * 16);
        }
        CP_COMMIT();
    };

    auto compute_tile = [&](int cur, int I, int J2) {
        const int Jblk = 2 * J2 + (wn >> 2);
        const bool active = (Jblk >= I);
        float pr[8], pc[8];
        #pragma unroll
        for (int h = 0; h < 8; h++) { pr[h] = 0.f; pc[h] = 0.f; }

        if (active) {
            uint32_t acc[4][4][2];
            #pragma unroll
            for (int mi = 0; mi < 4; mi++)
                #pragma unroll
                for (int ni = 0; ni < 4; ni++) {
                    acc[mi][ni][0] = 0u; acc[mi][ni][1] = 0u;
                }
            const uint32_t aT = bufA[cur] + aSel;
            const uint32_t bT = bufB[cur] + bSel;
            #pragma unroll
            for (int ks = 0; ks < 8; ks++) {
                uint32_t afr[4][4], bfr[2][4];
                #pragma unroll
                for (int mi = 0; mi < 4; mi++) {
                    uint32_t ad = aT + (uint32_t)(mi * 16 * TSTRIDE + ks * 32);
                    LDSM_X4(afr[mi][0], afr[mi][1], afr[mi][2], afr[mi][3], ad);
                }
                #pragma unroll
                for (int np = 0; np < 2; np++) {
                    uint32_t bd = bT + (uint32_t)(np * 16 * TSTRIDE + ks * 32);
                    LDSM_X4(bfr[np][0], bfr[np][1], bfr[np][2], bfr[np][3], bd);
                }
                #pragma unroll
                for (int mi = 0; mi < 4; mi++)
                    #pragma unroll
                    for (int ni = 0; ni < 4; ni++)
                        MMA16816H(acc[mi][ni], afr[mi],
                                  bfr[ni >> 1][(ni & 1) * 2],
                                  bfr[ni >> 1][(ni & 1) * 2 + 1]);
            }
            // Serial exp epilogue.
            #pragma unroll
            for (int mi = 0; mi < 4; mi++)
                #pragma unroll
                for (int ni = 0; ni < 4; ni++)
                    #pragma unroll
                    for (int rg = 0; rg < 2; rg++) {
                        float2 f = __half22float2(
                            *(const __half2*)&acc[mi][ni][rg]);
                        float e0 = ex2f(fmaf(f.x, K1, -K1));
                        float e1 = ex2f(fmaf(f.y, K1, -K1));
                        pr[mi * 2 + rg] += e0 + e1;
                        pc[ni * 2]     += e0;
                        pc[ni * 2 + 1] += e1;
                    }
            if (Jblk == I) {   // diagonal exclusion
                #pragma unroll
                for (int mi = 0; mi < 4; mi++)
                    #pragma unroll
                    for (int ni = 0; ni < 4; ni++)
                        #pragma unroll
                        for (int rg = 0; rg < 2; rg++) {
                            int rT = wm * 64 + mi * 16 + (lane >> 2) + 8 * rg;
                            int cB = (wn & 3) * 32 + ni * 8 + (lane & 3) * 2;
                            if (cB == rT || cB + 1 == rT) {
                                float2 f = __half22float2(
                                    *(const __half2*)&acc[mi][ni][rg]);
                                float fd = (cB == rT) ? f.x : f.y;
                                pr[mi * 2 + rg] -= ex2f(fmaf(fd, K1, -K1));
                            }
                        }
            }
        }

        // Warp reductions.
        #pragma unroll
        for (int h = 0; h < 8; h++) {
            pr[h] += __shfl_xor_sync(0xffffffffu, pr[h], 1);
            pr[h] += __shfl_xor_sync(0xffffffffu, pr[h], 2);
            pc[h] += __shfl_xor_sync(0xffffffffu, pc[h], 4);
            pc[h] += __shfl_xor_sync(0xffffffffu, pc[h], 8);
            pc[h] += __shfl_xor_sync(0xffffffffu, pc[h], 16);
        }
        if ((lane & 3) == 0) {
            #pragma unroll
            for (int h = 0; h < 8; h++) {
                int r = wm * 64 + (h >> 1) * 16 + (lane >> 2) + 8 * (h & 1);
                sRow[r * 9 + wn] = pr[h];
            }
        }
        if (lane < 4) {
            #pragma unroll
            for (int h = 0; h < 8; h++) {
                int c = wn * 32 + (h >> 1) * 8 + lane * 2 + (h & 1);
                sCol[c * 2 + wm] = pc[h];
            }
        }
        __syncthreads();   // also: all warps done reading buf cur

        const int JA = 2 * J2, JB = 2 * J2 + 1;
        if (tid < 128) {
            float vA = sRow[tid * 9 + 0] + sRow[tid * 9 + 1]
                     + sRow[tid * 9 + 2] + sRow[tid * 9 + 3];
            float vB = sRow[tid * 9 + 4] + sRow[tid * 9 + 5]
                     + sRow[tid * 9 + 6] + sRow[tid * 9 + 7];
            if (JA >= I) g_part[((size_t)I * NBLK + JA) * 128 + tid] = vA;
            g_part[((size_t)I * NBLK + JB) * 128 + tid] = vB;
        } else if (tid < 384) {
            int c  = tid - 128;
            int Jb = JA + (c >> 7);
            if (Jb > I)
                g_part[((size_t)Jb * NBLK + I) * 128 + (c & 127)] =
                    sCol[c * 2] + sCol[c * 2 + 1];
        }
    };

    // ---- pipeline ----
    int k = blockIdx.x;
    int I, J2, In, Jn;
    mapIJ(k, I, J2);
    issue_tile(I, J2, 0);
    int k1 = k + GRID;
    bool h1 = (k1 < TILES);
    if (h1) { mapIJ(k1, In, Jn); issue_tile(In, Jn, 1); CP_WAIT1(); }
    else    { CP_WAIT0(); }
    __syncthreads();

    int t = 0;
    while (true) {
        int cur = t & 1;
        compute_tile(cur, I, J2);
        if (k + GRID >= TILES) break;
        int k2 = k + 2 * GRID;
        int In2 = 0, Jn2 = 0;
        if (k2 < TILES) {
            mapIJ(k2, In2, Jn2);
            issue_tile(In2, Jn2, cur);
            CP_WAIT1();
        } else {
            CP_WAIT0();
        }
        __syncthreads();
        I = In; J2 = Jn; In = In2; Jn = Jn2;
        k += GRID; t++;
    }
}

// ---------------------------------------------------------------------------
// Kernel 3: row gather -> log_prob -> fused deterministic final sum.
// ---------------------------------------------------------------------------
__global__ void __launch_bounds__(256) reduce_kernel(float* __restrict__ out) {
    __shared__ double sm[256];
    __shared__ int isLast;
    int tid = threadIdx.x;
    int row = blockIdx.x * 256 + tid;
    int R = row >> 7, m = row & 127;
    float s = 0.f;
    #pragma unroll 8
    for (int O = 0; O < NBLK; O++)
        s += g_part[((size_t)R * NBLK + O) * 128 + m];
    sm[tid] = (double)(g_pos[row] - logf(s));
    __syncthreads();
    #pragma unroll
    for (int o = 128; o; o >>= 1) {
        if (tid < o) sm[tid] += sm[tid + o];
        __syncthreads();
    }
    if (tid == 0) {
        g_bsum[blockIdx.x] = sm[0];
        __threadfence();
        int old = atomicAdd(&g_ctr, 1);
        isLast = (old == 31);
    }
    __syncthreads();
    if (isLast && tid == 0) {
        double tot = 0.0;
        #pragma unroll
        for (int i = 0; i < 32; i++) tot += g_bsum[i];
        out[0] = (float)(-tot / (double)TWO_N);
        g_ctr = 0;   // reset for next graph replay
    }
}

// ---------------------------------------------------------------------------
extern "C" void kernel_launch(void* const* d_in, const int* in_sizes, int n_in,
                              void* d_out, int out_size) {
    const float* f1 = (const float*)d_in[0];
    const float* f2 = (const float*)d_in[1];
    float* out = (float*)d_out;

    cudaFuncSetAttribute(ntxent_mma_kernel,
                         cudaFuncAttributeMaxDynamicSharedMemorySize, SMEM_DYN);

    normalize_kernel<<<N_HALF / 8, 256>>>(f1, f2);
    ntxent_mma_kernel<<<GRID, 512, SMEM_DYN>>>();
    reduce_kernel<<<32, 256>>>(out);
}